// round 10
// baseline (speedup 1.0000x reference)
#include <cuda_runtime.h>

typedef unsigned long long ull;

#define BB 256
#define TT 2048

// layer-0 output: g_h1[(b*TT + t)*64 + dir*32 + cell]
__device__ float g_h1[(size_t)BB * TT * 64];

__device__ __forceinline__ float tanh_hw(float x) {
    float y;
    asm("tanh.approx.f32 %0, %1;" : "=f"(y) : "f"(x));
    return y;
}
__device__ __forceinline__ float sigh(float x) {
    return fmaf(tanh_hw(0.5f * x), 0.5f, 0.5f);
}
__device__ __forceinline__ void unpack2(ull v, float& lo, float& hi) {
    asm("mov.b64 {%0, %1}, %2;" : "=f"(lo), "=f"(hi) : "l"(v));
}
__device__ __forceinline__ ull ffma2(ull a, ull b, ull c) {
    ull d;
    asm("fma.rn.f32x2 %0, %1, %2, %3;" : "=l"(d) : "l"(a), "l"(b), "l"(c));
    return d;
}
__device__ __forceinline__ ull fadd2(ull a, ull b) {
    ull d;
    asm("add.rn.f32x2 %0, %1, %2;" : "=l"(d) : "l"(a), "l"(b));
    return d;
}

#define BARC(id) asm volatile("bar.sync %0, 96;" :: "r"(id) : "memory")

// ---------------------------------------------------------------------------
// Fused layer, 4 chains per 384-thread block (12 warps), 128 blocks (1/SM).
// Chain c = warps {c (consumer), 4+c (producer i,f), 8+c (producer g,o)} —
// all three on SMSP c: every SMSP carries the same 1-consumer+2-producer mix.
// Producers run one 4-step round ahead through an 8-slot xg ring; one named
// barrier (id c+1, 96 threads) per 4-step round. Producers read x with
// uniform-address LDGs (no staging). Consumer never touches global loads.
// ---------------------------------------------------------------------------
template<bool L0>
__global__ __launch_bounds__(384, 1)
void lstm_layer(const float* __restrict__ oseq,   // [B,T,16] (L0)
                const float* __restrict__ iseq,   // [B,T,16] (L0)
                const float* __restrict__ Wih,    // [2,128,F]
                const float* __restrict__ Whh,    // [2,128,32]
                const float* __restrict__ bih,    // [2,128]
                const float* __restrict__ bhh,    // [2,128]
                float* __restrict__ outp)         // L1: d_out [B,T,64]
{
    constexpr int F = L0 ? 32 : 64;
    const int dir   = blockIdx.y;
    const int wid   = threadIdx.x >> 5;
    const int lane  = threadIdx.x & 31;
    const int chain = wid & 3;
    const int role  = wid >> 2;          // 0: consumer, 1: prod{i,f}, 2: prod{g,o}
    const int b     = blockIdx.x * 4 + chain;
    const int barid = chain + 1;

    __shared__ __align__(16) float ring[4][8][32][4];   // [chain][slot][cell][gate]
    __shared__ __align__(16) float h_sh[4][32];

    if (role == 0) {
        // ========================= consumer =========================
        ull w[4][16];
        #pragma unroll
        for (int g = 0; g < 4; g++) {
            const ull* p = (const ull*)(Whh + (size_t)(dir * 128 + g * 32 + lane) * 32);
            #pragma unroll
            for (int k = 0; k < 16; k++) w[g][k] = p[k];
        }
        h_sh[chain][lane] = 0.0f;
        float c = 0.0f;
        __syncwarp();

        BARC(barid);   // round 0 produced

        float* const hout = L0 ? g_h1 : outp;
        const size_t orow = (size_t)b * TT;
        const int ocol = dir * 32 + lane;

        for (int r = 0; r < TT / 4; r++) {
            #pragma unroll
            for (int j = 0; j < 4; j++) {
                const int ss = r * 4 + j;
                const float4 xg4 = *(const float4*)&ring[chain][ss & 7][lane][0];

                const ulonglong2* hp = (const ulonglong2*)h_sh[chain];
                ull aA0 = 0, aB0 = 0, aA1 = 0, aB1 = 0;
                ull aA2 = 0, aB2 = 0, aA3 = 0, aB3 = 0;
                #pragma unroll
                for (int k = 0; k < 8; k++) {
                    const ulonglong2 hv = hp[k];
                    aA0 = ffma2(w[0][2 * k], hv.x, aA0); aB0 = ffma2(w[0][2 * k + 1], hv.y, aB0);
                    aA1 = ffma2(w[1][2 * k], hv.x, aA1); aB1 = ffma2(w[1][2 * k + 1], hv.y, aB1);
                    aA2 = ffma2(w[2][2 * k], hv.x, aA2); aB2 = ffma2(w[2][2 * k + 1], hv.y, aB2);
                    aA3 = ffma2(w[3][2 * k], hv.x, aA3); aB3 = ffma2(w[3][2 * k + 1], hv.y, aB3);
                }
                float lo, hi, gi, gf, gg, go;
                ull s0 = fadd2(aA0, aB0); unpack2(s0, lo, hi); gi = (lo + hi) + xg4.x;
                ull s1 = fadd2(aA1, aB1); unpack2(s1, lo, hi); gf = (lo + hi) + xg4.y;
                ull s2 = fadd2(aA2, aB2); unpack2(s2, lo, hi); gg = (lo + hi) + xg4.z;
                ull s3 = fadd2(aA3, aB3); unpack2(s3, lo, hi); go = (lo + hi) + xg4.w;

                const float fi = sigh(gi);
                const float ff = sigh(gf);
                const float tg = tanh_hw(gg);
                const float fo = sigh(go);
                c = fmaf(ff, c, fi * tg);
                const float h = fo * tanh_hw(c);

                h_sh[chain][lane] = h;
                __syncwarp();

                const int t = dir ? (TT - 1 - ss) : ss;
                hout[(orow + t) * 64 + ocol] = h;
            }
            BARC(barid);
        }
    } else {
        // ========================= producer =========================
        const int pw = role - 1;               // 0: gates i,f   1: gates g,o
        const int r0 = pw * 64 + lane;         // i or g row
        const int r1 = pw * 64 + 32 + lane;    // f or o row

        ull w0[F / 2], w1[F / 2];
        {
            const ull* p0 = (const ull*)(Wih + (size_t)(dir * 128 + r0) * F);
            const ull* p1 = (const ull*)(Wih + (size_t)(dir * 128 + r1) * F);
            #pragma unroll
            for (int k = 0; k < F / 2; k++) { w0[k] = p0[k]; w1[k] = p1[k]; }
        }
        const float bias0 = bih[dir * 128 + r0] + bhh[dir * 128 + r0];
        const float bias1 = bih[dir * 128 + r1] + bhh[dir * 128 + r1];

        auto produce = [&](int ss) {
            const int t = dir ? (TT - 1 - ss) : ss;
            ull a0 = 0, c0 = 0, a1 = 0, c1 = 0;
            if (L0) {
                const ulonglong2* xo = (const ulonglong2*)(oseq + ((size_t)b * TT + t) * 16);
                const ulonglong2* xi = (const ulonglong2*)(iseq + ((size_t)b * TT + (TT - 1 - t)) * 16);
                #pragma unroll
                for (int k = 0; k < 4; k++) {
                    const ulonglong2 v = xo[k];
                    a0 = ffma2(w0[2 * k],     v.x, a0);
                    c0 = ffma2(w0[2 * k + 1], v.y, c0);
                    a1 = ffma2(w1[2 * k],     v.x, a1);
                    c1 = ffma2(w1[2 * k + 1], v.y, c1);
                }
                #pragma unroll
                for (int k = 0; k < 4; k++) {
                    const ulonglong2 v = xi[k];
                    a0 = ffma2(w0[8 + 2 * k], v.x, a0);
                    c0 = ffma2(w0[9 + 2 * k], v.y, c0);
                    a1 = ffma2(w1[8 + 2 * k], v.x, a1);
                    c1 = ffma2(w1[9 + 2 * k], v.y, c1);
                }
            } else {
                const ulonglong2* xr = (const ulonglong2*)(g_h1 + ((size_t)b * TT + t) * 64);
                #pragma unroll
                for (int k = 0; k < 16; k++) {
                    const ulonglong2 v = xr[k];
                    a0 = ffma2(w0[2 * k],     v.x, a0);
                    c0 = ffma2(w0[2 * k + 1], v.y, c0);
                    a1 = ffma2(w1[2 * k],     v.x, a1);
                    c1 = ffma2(w1[2 * k + 1], v.y, c1);
                }
            }
            float lo, hi;
            float2 o;
            ull t0 = fadd2(a0, c0); unpack2(t0, lo, hi); o.x = (lo + hi) + bias0;
            ull t1 = fadd2(a1, c1); unpack2(t1, lo, hi); o.y = (lo + hi) + bias1;
            *(float2*)&ring[chain][ss & 7][lane][2 * pw] = o;
        };

        // round 0
        #pragma unroll
        for (int j = 0; j < 4; j++) produce(j);
        BARC(barid);

        for (int r = 0; r < TT / 4; r++) {
            if (r + 1 < TT / 4) {
                #pragma unroll
                for (int j = 0; j < 4; j++) produce(4 * (r + 1) + j);
            }
            BARC(barid);
        }
    }
}

extern "C" void kernel_launch(void* const* d_in, const int* in_sizes, int n_in,
                              void* d_out, int out_size) {
    (void)in_sizes; (void)n_in; (void)out_size;
    const float* oseq = (const float*)d_in[0];
    const float* iseq = (const float*)d_in[1];
    const float* Wih0 = (const float*)d_in[2];
    const float* Whh0 = (const float*)d_in[3];
    const float* bih0 = (const float*)d_in[4];
    const float* bhh0 = (const float*)d_in[5];
    const float* Wih1 = (const float*)d_in[6];
    const float* Whh1 = (const float*)d_in[7];
    const float* bih1 = (const float*)d_in[8];
    const float* bhh1 = (const float*)d_in[9];
    float* out = (float*)d_out;

    lstm_layer<true ><<<dim3(64, 2), 384>>>(oseq, iseq, Wih0, Whh0, bih0, bhh0, nullptr);
    lstm_layer<false><<<dim3(64, 2), 384>>>(nullptr, nullptr, Wih1, Whh1, bih1, bhh1, out);
}

// round 11
// speedup vs baseline: 2.8696x; 2.8696x over previous
#include <cuda_runtime.h>

typedef unsigned long long ull;

#define BB 256
#define TT 2048

// layer-0 output: g_h1[(b*TT + t)*64 + dir*32 + cell]
__device__ float g_h1[(size_t)BB * TT * 64];

__device__ __forceinline__ float tanh_hw(float x) {
    float y;
    asm("tanh.approx.f32 %0, %1;" : "=f"(y) : "f"(x));
    return y;
}
__device__ __forceinline__ float sigh(float x) {
    return fmaf(tanh_hw(0.5f * x), 0.5f, 0.5f);
}
__device__ __forceinline__ void unpack2(ull v, float& lo, float& hi) {
    asm("mov.b64 {%0, %1}, %2;" : "=f"(lo), "=f"(hi) : "l"(v));
}
__device__ __forceinline__ ull ffma2(ull a, ull b, ull c) {
    ull d;
    asm("fma.rn.f32x2 %0, %1, %2, %3;" : "=l"(d) : "l"(a), "l"(b), "l"(c));
    return d;
}
__device__ __forceinline__ ull fadd2(ull a, ull b) {
    ull d;
    asm("add.rn.f32x2 %0, %1, %2;" : "=l"(d) : "l"(a), "l"(b));
    return d;
}

#define BARC(id) asm volatile("bar.sync %0, 96;" :: "r"(id) : "memory")

// ---------------------------------------------------------------------------
// Fused layer, 4 chains per 384-thread block (12 warps), 128 blocks (1/SM).
// Chain c = warps {c: consumer, 4+c: producer{i,f}, 8+c: producer{g,o}}.
// Named barrier (id c+1, 96 threads) once per 4-step round.
// Producer round r:  LDG x for round r+2 (coalesced, lanes split the vector)
//                    -> produce round r+1 gates from smem x-ring (LDS only)
//                    -> STS the arrived x into the ring.
// Consumer: pure LDS/ffma2/MUFU recurrence; no global loads ever.
// ---------------------------------------------------------------------------
template<bool L0>
__global__ __launch_bounds__(384, 1)
void lstm_layer(const float* __restrict__ oseq,   // [B,T,16] (L0)
                const float* __restrict__ iseq,   // [B,T,16] (L0)
                const float* __restrict__ Wih,    // [2,128,F]
                const float* __restrict__ Whh,    // [2,128,32]
                const float* __restrict__ bih,    // [2,128]
                const float* __restrict__ bhh,    // [2,128]
                float* __restrict__ outp)         // L1: d_out [B,T,64]
{
    constexpr int F  = L0 ? 32 : 64;
    constexpr int NR = TT / 4;           // rounds
    const int dir   = blockIdx.y;
    const int wid   = threadIdx.x >> 5;
    const int lane  = threadIdx.x & 31;
    const int chain = wid & 3;
    const int role  = wid >> 2;          // 0: consumer, 1: prod{i,f}, 2: prod{g,o}
    const int b     = blockIdx.x * 4 + chain;
    const int barid = chain + 1;

    __shared__ __align__(16) float ring[4][8][32][4];    // [chain][slot][cell][gate]
    __shared__ __align__(16) float xring[4][2][8][F];    // [chain][pw][slot][feat]
    __shared__ __align__(16) float h_sh[4][32];

    if (role == 0) {
        // ========================= consumer =========================
        ull w[4][16];
        #pragma unroll
        for (int g = 0; g < 4; g++) {
            const ull* p = (const ull*)(Whh + (size_t)(dir * 128 + g * 32 + lane) * 32);
            #pragma unroll
            for (int k = 0; k < 16; k++) w[g][k] = p[k];
        }
        h_sh[chain][lane] = 0.0f;
        float c = 0.0f;
        __syncwarp();

        BARC(barid);   // round 0 produced

        float* const hout = L0 ? g_h1 : outp;
        const size_t orow = (size_t)b * TT;
        const int ocol = dir * 32 + lane;

        for (int r = 0; r < NR; r++) {
            #pragma unroll
            for (int j = 0; j < 4; j++) {
                const int ss = r * 4 + j;
                const float4 xg4 = *(const float4*)&ring[chain][ss & 7][lane][0];

                const ulonglong2* hp = (const ulonglong2*)h_sh[chain];
                ull aA0 = 0, aB0 = 0, aA1 = 0, aB1 = 0;
                ull aA2 = 0, aB2 = 0, aA3 = 0, aB3 = 0;
                #pragma unroll
                for (int k = 0; k < 8; k++) {
                    const ulonglong2 hv = hp[k];
                    aA0 = ffma2(w[0][2 * k], hv.x, aA0); aB0 = ffma2(w[0][2 * k + 1], hv.y, aB0);
                    aA1 = ffma2(w[1][2 * k], hv.x, aA1); aB1 = ffma2(w[1][2 * k + 1], hv.y, aB1);
                    aA2 = ffma2(w[2][2 * k], hv.x, aA2); aB2 = ffma2(w[2][2 * k + 1], hv.y, aB2);
                    aA3 = ffma2(w[3][2 * k], hv.x, aA3); aB3 = ffma2(w[3][2 * k + 1], hv.y, aB3);
                }
                float lo, hi, gi, gf, gg, go;
                ull s0 = fadd2(aA0, aB0); unpack2(s0, lo, hi); gi = (lo + hi) + xg4.x;
                ull s1 = fadd2(aA1, aB1); unpack2(s1, lo, hi); gf = (lo + hi) + xg4.y;
                ull s2 = fadd2(aA2, aB2); unpack2(s2, lo, hi); gg = (lo + hi) + xg4.z;
                ull s3 = fadd2(aA3, aB3); unpack2(s3, lo, hi); go = (lo + hi) + xg4.w;

                const float fi = sigh(gi);
                const float ff = sigh(gf);
                const float tg = tanh_hw(gg);
                const float fo = sigh(go);
                c = fmaf(ff, c, fi * tg);
                const float h = fo * tanh_hw(c);

                h_sh[chain][lane] = h;
                __syncwarp();

                const int t = dir ? (TT - 1 - ss) : ss;
                hout[(orow + t) * 64 + ocol] = h;
            }
            BARC(barid);
        }
    } else {
        // ========================= producer =========================
        const int pw = role - 1;               // 0: gates i,f   1: gates g,o
        const int r0 = pw * 64 + lane;         // i or g row
        const int r1 = pw * 64 + 32 + lane;    // f or o row

        ull w0[F / 2], w1[F / 2];
        {
            const ull* p0 = (const ull*)(Wih + (size_t)(dir * 128 + r0) * F);
            const ull* p1 = (const ull*)(Wih + (size_t)(dir * 128 + r1) * F);
            #pragma unroll
            for (int k = 0; k < F / 2; k++) { w0[k] = p0[k]; w1[k] = p1[k]; }
        }
        const float bias0 = bih[dir * 128 + r0] + bhh[dir * 128 + r0];
        const float bias1 = bih[dir * 128 + r1] + bhh[dir * 128 + r1];

        float* const myx = &xring[chain][pw][0][0];

        // coalesced load of this lane's share of x for chain-step ss (clamped)
        auto ldx = [&](int ss, float2& v) {
            ss = ss < TT - 1 ? ss : TT - 1;
            const int t = dir ? (TT - 1 - ss) : ss;
            if (L0) {
                // 32 floats: lanes 0-15 oseq[t], lanes 16-31 iseq[TT-1-t]
                if (lane < 16) v.x = oseq[((size_t)b * TT + t) * 16 + lane];
                else           v.x = iseq[((size_t)b * TT + (TT - 1 - t)) * 16 + (lane - 16)];
                v.y = 0.0f;
            } else {
                v = *(const float2*)(g_h1 + ((size_t)b * TT + t) * 64 + 2 * lane);
            }
        };
        auto stx = [&](int ss, const float2& v) {
            const int slot = ss & 7;
            if (L0) myx[slot * F + lane] = v.x;
            else    *(float2*)&myx[slot * F + 2 * lane] = v;
        };

        auto produce = [&](int ss) {
            const ulonglong2* xp = (const ulonglong2*)&myx[(ss & 7) * F];
            ull a0 = 0, c0 = 0, a1 = 0, c1 = 0;
            #pragma unroll
            for (int k = 0; k < F / 4; k++) {
                const ulonglong2 v = xp[k];
                a0 = ffma2(w0[2 * k],     v.x, a0);
                c0 = ffma2(w0[2 * k + 1], v.y, c0);
                a1 = ffma2(w1[2 * k],     v.x, a1);
                c1 = ffma2(w1[2 * k + 1], v.y, c1);
            }
            float lo, hi;
            float2 o;
            ull t0 = fadd2(a0, c0); unpack2(t0, lo, hi); o.x = (lo + hi) + bias0;
            ull t1 = fadd2(a1, c1); unpack2(t1, lo, hi); o.y = (lo + hi) + bias1;
            *(float2*)&ring[chain][ss & 7][lane][2 * pw] = o;
        };

        // prologue: x for steps 0..7 into the ring; produce round 0 (steps 0-3)
        {
            float2 v[8];
            #pragma unroll
            for (int j = 0; j < 8; j++) ldx(j, v[j]);
            #pragma unroll
            for (int j = 0; j < 8; j++) stx(j, v[j]);
            __syncwarp();
            #pragma unroll
            for (int j = 0; j < 4; j++) produce(j);
        }
        BARC(barid);

        for (int r = 0; r < NR; r++) {
            // 1) issue LDGs for round r+2's x (steps 4r+8..4r+11, clamped)
            float2 pend[4];
            #pragma unroll
            for (int j = 0; j < 4; j++) ldx(4 * r + 8 + j, pend[j]);

            // 2) produce round r+1 from the ring (LDS only)
            if (r + 1 < NR) {
                #pragma unroll
                for (int j = 0; j < 4; j++) produce(4 * (r + 1) + j);
            }

            // 3) store the arrived x into the ring (read in round r+1)
            #pragma unroll
            for (int j = 0; j < 4; j++) stx(4 * r + 8 + j, pend[j]);
            __syncwarp();

            BARC(barid);
        }
    }
}

extern "C" void kernel_launch(void* const* d_in, const int* in_sizes, int n_in,
                              void* d_out, int out_size) {
    (void)in_sizes; (void)n_in; (void)out_size;
    const float* oseq = (const float*)d_in[0];
    const float* iseq = (const float*)d_in[1];
    const float* Wih0 = (const float*)d_in[2];
    const float* Whh0 = (const float*)d_in[3];
    const float* bih0 = (const float*)d_in[4];
    const float* bhh0 = (const float*)d_in[5];
    const float* Wih1 = (const float*)d_in[6];
    const float* Whh1 = (const float*)d_in[7];
    const float* bih1 = (const float*)d_in[8];
    const float* bhh1 = (const float*)d_in[9];
    float* out = (float*)d_out;

    lstm_layer<true ><<<dim3(64, 2), 384>>>(oseq, iseq, Wih0, Whh0, bih0, bhh0, nullptr);
    lstm_layer<false><<<dim3(64, 2), 384>>>(nullptr, nullptr, Wih1, Whh1, bih1, bhh1, out);
}

// round 12
// speedup vs baseline: 2.9150x; 1.0158x over previous
#include <cuda_runtime.h>

typedef unsigned long long ull;

#define BB 256
#define TT 2048

// layer-0 output: g_h1[(b*TT + t)*64 + dir*32 + cell]
__device__ float g_h1[(size_t)BB * TT * 64];

__device__ __forceinline__ float tanh_hw(float x) {
    float y;
    asm("tanh.approx.f32 %0, %1;" : "=f"(y) : "f"(x));
    return y;
}
__device__ __forceinline__ ull pack2(float lo, float hi) {
    ull r;
    asm("mov.b64 %0, {%1, %2};" : "=l"(r) : "f"(lo), "f"(hi));
    return r;
}
__device__ __forceinline__ void unpack2(ull v, float& lo, float& hi) {
    asm("mov.b64 {%0, %1}, %2;" : "=f"(lo), "=f"(hi) : "l"(v));
}
__device__ __forceinline__ ull ffma2(ull a, ull b, ull c) {
    ull d;
    asm("fma.rn.f32x2 %0, %1, %2, %3;" : "=l"(d) : "l"(a), "l"(b), "l"(c));
    return d;
}
__device__ __forceinline__ ull fadd2(ull a, ull b) {
    ull d;
    asm("add.rn.f32x2 %0, %1, %2;" : "=l"(d) : "l"(a), "l"(b));
    return d;
}

#define BARC(id) asm volatile("bar.sync %0, 96;" :: "r"(id) : "memory")

// ---------------------------------------------------------------------------
// Fused layer, 4 chains per 384-thread block (12 warps), 128 blocks (1/SM).
// ARBITER-AWARE warp placement (hi-wid-first issue priority per SMSP):
//   wid 0-3  : producer{i,f} for chain (wid&3)     (lowest priority)
//   wid 4-7  : producer{g,o} for chain (wid&3)
//   wid 8-11 : CONSUMER      for chain (wid&3)     (highest priority)
// All three warps of chain c land on SMSP c. The consumer's serial recurrence
// path always wins arbitration; producers fill its stall bubbles.
// Sigmoid input scale 0.5 is folded into W_ih/W_hh/bias for gates i,f,o.
// xg is folded into the consumer's accumulator init.
// ---------------------------------------------------------------------------
template<bool L0>
__global__ __launch_bounds__(384, 1)
void lstm_layer(const float* __restrict__ oseq,   // [B,T,16] (L0)
                const float* __restrict__ iseq,   // [B,T,16] (L0)
                const float* __restrict__ Wih,    // [2,128,F]
                const float* __restrict__ Whh,    // [2,128,32]
                const float* __restrict__ bih,    // [2,128]
                const float* __restrict__ bhh,    // [2,128]
                float* __restrict__ outp)         // L1: d_out [B,T,64]
{
    constexpr int F  = L0 ? 32 : 64;
    constexpr int NR = TT / 4;           // rounds of 4 steps
    const int dir   = blockIdx.y;
    const int wid   = threadIdx.x >> 5;
    const int lane  = threadIdx.x & 31;
    const int chain = wid & 3;
    const int role  = wid >> 2;          // 0: prod{i,f}, 1: prod{g,o}, 2: consumer
    const int b     = blockIdx.x * 4 + chain;
    const int barid = chain + 1;

    __shared__ __align__(16) float ring[4][8][32][4];    // [chain][slot][cell][gate]
    __shared__ __align__(16) float xring[4][2][8][F];    // [chain][pw][slot][feat]
    __shared__ __align__(16) float h_sh[4][32];

    if (role == 2) {
        // ========================= consumer (hi-wid) =========================
        // W_hh rows for gates i(0), f(1), o(3) pre-scaled by 0.5.
        ull w[4][16];
        #pragma unroll
        for (int g = 0; g < 4; g++) {
            const float2* p = (const float2*)(Whh + (size_t)(dir * 128 + g * 32 + lane) * 32);
            const float sc = (g == 2) ? 1.0f : 0.5f;
            #pragma unroll
            for (int k = 0; k < 16; k++) {
                const float2 v = p[k];
                w[g][k] = pack2(v.x * sc, v.y * sc);
            }
        }
        h_sh[chain][lane] = 0.0f;
        float c = 0.0f;
        __syncwarp();

        BARC(barid);   // round 0 produced

        float* const hout = L0 ? g_h1 : outp;
        const size_t orow = (size_t)b * TT;
        const int ocol = dir * 32 + lane;

        for (int r = 0; r < NR; r++) {
            #pragma unroll
            for (int j = 0; j < 4; j++) {
                const int ss = r * 4 + j;
                const float4 xg4 = *(const float4*)&ring[chain][ss & 7][lane][0];

                const ulonglong2* hp = (const ulonglong2*)h_sh[chain];
                ull aA0 = pack2(xg4.x, 0.0f), aB0 = 0ull;
                ull aA1 = pack2(xg4.y, 0.0f), aB1 = 0ull;
                ull aA2 = pack2(xg4.z, 0.0f), aB2 = 0ull;
                ull aA3 = pack2(xg4.w, 0.0f), aB3 = 0ull;
                #pragma unroll
                for (int k = 0; k < 8; k++) {
                    const ulonglong2 hv = hp[k];
                    aA0 = ffma2(w[0][2 * k], hv.x, aA0); aB0 = ffma2(w[0][2 * k + 1], hv.y, aB0);
                    aA1 = ffma2(w[1][2 * k], hv.x, aA1); aB1 = ffma2(w[1][2 * k + 1], hv.y, aB1);
                    aA2 = ffma2(w[2][2 * k], hv.x, aA2); aB2 = ffma2(w[2][2 * k + 1], hv.y, aB2);
                    aA3 = ffma2(w[3][2 * k], hv.x, aA3); aB3 = ffma2(w[3][2 * k + 1], hv.y, aB3);
                }
                float lo, hi, gi, gf, gg, go;
                ull s0 = fadd2(aA0, aB0); unpack2(s0, lo, hi); gi = lo + hi;
                ull s1 = fadd2(aA1, aB1); unpack2(s1, lo, hi); gf = lo + hi;
                ull s2 = fadd2(aA2, aB2); unpack2(s2, lo, hi); gg = lo + hi;
                ull s3 = fadd2(aA3, aB3); unpack2(s3, lo, hi); go = lo + hi;

                // inputs for i,f,o already halved (weights/bias folded)
                const float fi = fmaf(tanh_hw(gi), 0.5f, 0.5f);
                const float ff = fmaf(tanh_hw(gf), 0.5f, 0.5f);
                const float tg = tanh_hw(gg);
                const float fo = fmaf(tanh_hw(go), 0.5f, 0.5f);
                c = fmaf(ff, c, fi * tg);
                const float h = fo * tanh_hw(c);

                h_sh[chain][lane] = h;
                __syncwarp();

                const int t = dir ? (TT - 1 - ss) : ss;
                hout[(orow + t) * 64 + ocol] = h;
            }
            BARC(barid);
        }
    } else {
        // ========================= producer (lo-wid) =========================
        const int pw = role;                   // 0: gates i,f   1: gates g,o
        const int r0 = pw * 64 + lane;         // i or g row
        const int r1 = pw * 64 + 32 + lane;    // f or o row
        // sigmoid-input fold: rows i,f (pw0 both) and o (pw1 r1) scaled by 0.5
        const float sc0 = (pw == 0) ? 0.5f : 1.0f;
        const float sc1 = 0.5f;

        ull w0[F / 2], w1[F / 2];
        {
            const float2* p0 = (const float2*)(Wih + (size_t)(dir * 128 + r0) * F);
            const float2* p1 = (const float2*)(Wih + (size_t)(dir * 128 + r1) * F);
            #pragma unroll
            for (int k = 0; k < F / 2; k++) {
                const float2 a = p0[k], bv = p1[k];
                w0[k] = pack2(a.x * sc0, a.y * sc0);
                w1[k] = pack2(bv.x * sc1, bv.y * sc1);
            }
        }
        const float bias0 = (bih[dir * 128 + r0] + bhh[dir * 128 + r0]) * sc0;
        const float bias1 = (bih[dir * 128 + r1] + bhh[dir * 128 + r1]) * sc1;

        float* const myx = &xring[chain][pw][0][0];

        auto ldx = [&](int ss, float2& v) {
            ss = ss < TT - 1 ? ss : TT - 1;
            const int t = dir ? (TT - 1 - ss) : ss;
            if (L0) {
                if (lane < 16) v.x = oseq[((size_t)b * TT + t) * 16 + lane];
                else           v.x = iseq[((size_t)b * TT + (TT - 1 - t)) * 16 + (lane - 16)];
                v.y = 0.0f;
            } else {
                v = *(const float2*)(g_h1 + ((size_t)b * TT + t) * 64 + 2 * lane);
            }
        };
        auto stx = [&](int ss, const float2& v) {
            const int slot = ss & 7;
            if (L0) myx[slot * F + lane] = v.x;
            else    *(float2*)&myx[slot * F + 2 * lane] = v;
        };

        auto produce = [&](int ss) {
            const ulonglong2* xp = (const ulonglong2*)&myx[(ss & 7) * F];
            ull a0 = 0, c0 = 0, a1 = 0, c1 = 0;
            #pragma unroll
            for (int k = 0; k < F / 4; k++) {
                const ulonglong2 v = xp[k];
                a0 = ffma2(w0[2 * k],     v.x, a0);
                c0 = ffma2(w0[2 * k + 1], v.y, c0);
                a1 = ffma2(w1[2 * k],     v.x, a1);
                c1 = ffma2(w1[2 * k + 1], v.y, c1);
            }
            float lo, hi;
            float2 o;
            ull t0 = fadd2(a0, c0); unpack2(t0, lo, hi); o.x = (lo + hi) + bias0;
            ull t1 = fadd2(a1, c1); unpack2(t1, lo, hi); o.y = (lo + hi) + bias1;
            *(float2*)&ring[chain][ss & 7][lane][2 * pw] = o;
        };

        // prologue: x for steps 0..7; produce round 0 (steps 0-3)
        {
            float2 v[8];
            #pragma unroll
            for (int j = 0; j < 8; j++) ldx(j, v[j]);
            #pragma unroll
            for (int j = 0; j < 8; j++) stx(j, v[j]);
            __syncwarp();
            #pragma unroll
            for (int j = 0; j < 4; j++) produce(j);
        }
        BARC(barid);

        for (int r = 0; r < NR; r++) {
            // 1) LDGs for round r+2's x
            float2 pend[4];
            #pragma unroll
            for (int j = 0; j < 4; j++) ldx(4 * r + 8 + j, pend[j]);

            // 2) produce round r+1 (LDS only)
            if (r + 1 < NR) {
                #pragma unroll
                for (int j = 0; j < 4; j++) produce(4 * (r + 1) + j);
            }

            // 3) commit arrived x
            #pragma unroll
            for (int j = 0; j < 4; j++) stx(4 * r + 8 + j, pend[j]);
            __syncwarp();

            BARC(barid);
        }
    }
}

extern "C" void kernel_launch(void* const* d_in, const int* in_sizes, int n_in,
                              void* d_out, int out_size) {
    (void)in_sizes; (void)n_in; (void)out_size;
    const float* oseq = (const float*)d_in[0];
    const float* iseq = (const float*)d_in[1];
    const float* Wih0 = (const float*)d_in[2];
    const float* Whh0 = (const float*)d_in[3];
    const float* bih0 = (const float*)d_in[4];
    const float* bhh0 = (const float*)d_in[5];
    const float* Wih1 = (const float*)d_in[6];
    const float* Whh1 = (const float*)d_in[7];
    const float* bih1 = (const float*)d_in[8];
    const float* bhh1 = (const float*)d_in[9];
    float* out = (float*)d_out;

    lstm_layer<true ><<<dim3(64, 2), 384>>>(oseq, iseq, Wih0, Whh0, bih0, bhh0, nullptr);
    lstm_layer<false><<<dim3(64, 2), 384>>>(nullptr, nullptr, Wih1, Whh1, bih1, bhh1, out);
}